// round 13
// baseline (speedup 1.0000x reference)
#include <cuda_runtime.h>
#include <cuda_bf16.h>
#include <cstdint>

#define NB   4096
#define DIN  784
#define NH   128
#define DL   8
#define NC   16
#define CH   32
#define DOUT 10
#define NCHUNK 16
#define TSTEPS 5

// lateral tiling
#define ITILE 128
#define KC    64
#define NJS   16
#define JRANGE (NB/NJS)     // 256
#define NCH   (JRANGE/KC)   // 4

#define HT_ROW 144              // 72 bf16 per hT row (padded, conflict-free LDS)
#define HT_CHUNK (CH*HT_ROW)    // 4608 B per 64-j chunk
#define ZJ_ROW 48               // 24 bf16 per zj row (16 used)

// ---------------- scratch ----------------
__device__ __align__(16) float g_z[NB*DL];
__device__ float g_sq[NB];                       // CI * |z|^2
__device__ __align__(16) __nv_bfloat16 g_zhl[NB*16];   // [hi0..hi7, lo0..lo7]
__device__ __align__(16) float g_hpre[NB*CH];
__device__ __align__(16) char  g_hT[(NB/KC)*HT_CHUNK]; // bf16 [chunk][ch][72]
__device__ __align__(16) float g_part[(size_t)NCHUNK*NB*CH];

// ---------------- math helpers ----------
__device__ __forceinline__ float ex2f(float x){
    float y; asm("ex2.approx.f32 %0, %1;" : "=f"(y) : "f"(x)); return y;
}
__device__ __forceinline__ float rcp_acc(float x){
    float r; asm("rcp.approx.f32 %0, %1;" : "=f"(r) : "f"(x));
    return r * fmaf(-x, r, 2.0f);
}
__device__ __forceinline__ float rsqrt_acc(float x){
    float r; asm("rsqrt.approx.f32 %0, %1;" : "=f"(r) : "f"(x));
    float e = x * r;
    return r * fmaf(-0.5f, e * r, 1.5f);
}
__device__ __forceinline__ float tanh_acc(float x){
    float ax = fabsf(x);
    float t  = ex2f(-2.8853900817779268f * ax);
    float y  = (1.0f - t) * rcp_acc(1.0f + t);
    return copysignf(y, x);
}

#define CI_F   (-0.50093577808644655f)
#define M2CI_F ( 1.0018715561728931f)

__device__ __forceinline__ uint32_t smem_u32(const void* p){
    uint32_t a;
    asm("{ .reg .u64 t; cvta.to.shared.u64 t, %1; cvt.u32.u64 %0, t; }" : "=r"(a) : "l"(p));
    return a;
}
#define MMA16816(c0,c1,c2,c3,a0,a1,a2,a3,b0,b1) \
    asm volatile("mma.sync.aligned.m16n8k16.row.col.f32.bf16.bf16.f32 " \
        "{%0,%1,%2,%3}, {%4,%5,%6,%7}, {%8,%9}, {%0,%1,%2,%3};" \
        : "+f"(c0),"+f"(c1),"+f"(c2),"+f"(c3) \
        : "r"(a0),"r"(a1),"r"(a2),"r"(a3),"r"(b0),"r"(b1))
#define CVT_BF2(d,hi,lo) asm("cvt.rn.satfinite.bf16x2.f32 %0, %1, %2;" : "=r"(d) : "f"(hi), "f"(lo))
#define LDS32(d, addr) asm volatile("ld.shared.b32 %0, [%1];" : "=r"(d) : "r"(addr))
#define CP16(dst, src) asm volatile("cp.async.cg.shared.global [%0], [%1], 16;" :: "r"(dst), "l"(src) : "memory")
#define CP4(dst, src)  asm volatile("cp.async.ca.shared.global [%0], [%1], 4;"  :: "r"(dst), "l"(src) : "memory")
#define CPCOMMIT() asm volatile("cp.async.commit_group;" ::: "memory")
#define CPWAIT0()  asm volatile("cp.async.wait_group 0;" ::: "memory")

// ---- pm field (4 steps), 8 threads per row (2 centers each) ----
__device__ __forceinline__ void pm_oct(float zr[DL], const float* cs,
                                       const float* ms, int o)
{
    #pragma unroll
    for (int step=0; step<4; step++){
        float n = 0.f;
        float g[DL] = {0.f,0.f,0.f,0.f,0.f,0.f,0.f,0.f};
        #pragma unroll
        for (int cc=0;cc<2;cc++){
            int c = o*2 + cc;
            float rv[DL]; float r2 = 1e-4f;
            #pragma unroll
            for (int k=0;k<DL;k++){ rv[k] = zr[k]-cs[c*DL+k]; r2 = fmaf(rv[k],rv[k],r2); }
            float rinv = rsqrt_acc(r2);
            float mr = ms[c]*rinv;
            n += mr;
            float w = mr*rinv*rinv;
            #pragma unroll
            for (int k=0;k<DL;k++) g[k] = fmaf(-w, rv[k], g[k]);
        }
        #pragma unroll
        for (int off=1; off<8; off<<=1){
            n += __shfl_xor_sync(0xffffffffu, n, off);
            #pragma unroll
            for (int k=0;k<DL;k++) g[k] += __shfl_xor_sync(0xffffffffu, g[k], off);
        }
        float s = 0.15f * rcp_acc(n + 1.0f);
        #pragma unroll
        for (int k=0;k<DL;k++)
            zr[k] = fminf(fmaxf(fmaf(s, g[k], zr[k]), -3.f), 3.f);
    }
}

__device__ __forceinline__ void z_store(const float zr[DL], int row)
{
    float s2 = 0.f;
    #pragma unroll
    for (int k=0;k<DL;k++) s2 = fmaf(zr[k], zr[k], s2);
    g_sq[row] = CI_F * s2;
    *(float4*)&g_z[row*DL]   = make_float4(zr[0],zr[1],zr[2],zr[3]);
    *(float4*)&g_z[row*DL+4] = make_float4(zr[4],zr[5],zr[6],zr[7]);
    __nv_bfloat16 hi[8], lo[8];
    #pragma unroll
    for (int k=0;k<DL;k++){
        hi[k] = __float2bfloat16(zr[k]);
        lo[k] = __float2bfloat16(zr[k] - __bfloat162float(hi[k]));
    }
    __nv_bfloat16* dst = &g_zhl[row*16];
    *(uint4*)dst       = *(uint4*)hi;
    *(uint4*)(dst + 8) = *(uint4*)lo;
}

__device__ __forceinline__ void h_update4(const float zr[DL], const float* wps,
                                          const float* bps, int row, int c0,
                                          float4 hc)
{
    float a4[4];
    #pragma unroll
    for (int u=0;u<4;u++) a4[u] = bps[c0+u];
    #pragma unroll
    for (int k=0;k<DL;k++){
        float zk = zr[k];
        #pragma unroll
        for (int u=0;u<4;u++) a4[u] = fmaf(zk, wps[k*CH + c0 + u], a4[u]);
    }
    float4 hv;
    hv.x = fmaf(0.9f, hc.x, 0.1f*tanh_acc(a4[0]));
    hv.y = fmaf(0.9f, hc.y, 0.1f*tanh_acc(a4[1]));
    hv.z = fmaf(0.9f, hc.z, 0.1f*tanh_acc(a4[2]));
    hv.w = fmaf(0.9f, hc.w, 0.1f*tanh_acc(a4[3]));
    *(float4*)&g_hpre[(size_t)row*CH + c0] = hv;
    int jl = row & 63;
    char* base = g_hT + (size_t)(row >> 6) * HT_CHUNK + jl*2;
    *(__nv_bfloat16*)(base + (c0+0)*HT_ROW) = __float2bfloat16(hv.x);
    *(__nv_bfloat16*)(base + (c0+1)*HT_ROW) = __float2bfloat16(hv.y);
    *(__nv_bfloat16*)(base + (c0+2)*HT_ROW) = __float2bfloat16(hv.z);
    *(__nv_bfloat16*)(base + (c0+3)*HT_ROW) = __float2bfloat16(hv.w);
}

// ---------------- encoder (scalar fp32, 16 rows/CTA) + fused prep tail ----------------
__global__ __launch_bounds__(256) void enc_kernel(
    const float* __restrict__ x, const float* __restrict__ W1,
    const float* __restrict__ b1, const float* __restrict__ W2,
    const float* __restrict__ b2,
    const float* __restrict__ centers, const float* __restrict__ mus,
    const float* __restrict__ Wp, const float* __restrict__ bp)
{
    __shared__ float xs[16][33];
    __shared__ __align__(16) float ws[32][NH];
    __shared__ float hs[16][NH+1];
    __shared__ float w2s[NH*DL];
    __shared__ float zs[16][DL];
    __shared__ float cs[NC*DL];
    __shared__ float ms[NC];
    __shared__ float wps[DL*CH];
    __shared__ float bps[CH];

    const int tid = threadIdx.x;
    const int rowBase = blockIdx.x * 16;
    const int rg = tid >> 4;     // 0..15 -> 1 row each
    const int cg = tid & 15;     // 0..15 -> 8 cols each

    for (int t = tid; t < NH*DL; t += 256) w2s[t] = W2[t];
    if (tid < NC*DL) cs[tid] = centers[tid];
    if (tid < NC) ms[tid] = mus[tid];
    for (int t = tid; t < DL*CH; t += 256) wps[t] = Wp[t];
    if (tid < CH) bps[tid] = bp[tid];

    float acc[8];
    #pragma unroll
    for (int u=0;u<8;u++) acc[u]=0.f;

    for (int k0 = 0; k0 < DIN; k0 += 32) {
        for (int t = tid; t < 16*32; t += 256) {
            int r = t >> 5, k = t & 31;
            int kk = k0 + k;
            xs[r][k] = (kk < DIN) ? x[(size_t)(rowBase + r)*DIN + kk] : 0.f;
        }
        for (int t = tid; t < 32*NH; t += 256) {
            int k = t >> 7, c = t & (NH-1);
            int kk = k0 + k;
            ws[k][c] = (kk < DIN) ? W1[(size_t)kk*NH + c] : 0.f;
        }
        __syncthreads();
        #pragma unroll
        for (int kk = 0; kk < 32; kk++) {
            float x0 = xs[rg][kk];
            float4 w0 = *(const float4*)&ws[kk][cg*8];
            float4 w1 = *(const float4*)&ws[kk][cg*8+4];
            acc[0] = fmaf(x0, w0.x, acc[0]);
            acc[1] = fmaf(x0, w0.y, acc[1]);
            acc[2] = fmaf(x0, w0.z, acc[2]);
            acc[3] = fmaf(x0, w0.w, acc[3]);
            acc[4] = fmaf(x0, w1.x, acc[4]);
            acc[5] = fmaf(x0, w1.y, acc[5]);
            acc[6] = fmaf(x0, w1.z, acc[6]);
            acc[7] = fmaf(x0, w1.w, acc[7]);
        }
        __syncthreads();
    }
    #pragma unroll
    for (int u=0;u<8;u++){
        int c = cg*8+u;
        hs[rg][c] = tanh_acc(acc[u] + b1[c]);
    }
    __syncthreads();
    if (tid < 128){
        int r = tid >> 3;   // 0..15
        int o = tid & 7;
        float s = b2[o];
        #pragma unroll 16
        for (int k=0;k<NH;k++) s = fmaf(hs[r][k], w2s[k*DL+o], s);
        zs[r][o] = s;
    }
    __syncthreads();

    // ---- fused prep tail: pm(z), side-products, hpre (h = 0) ----
    if (tid < 128){
        const int r = tid >> 3;
        const int o = tid & 7;
        const int row = rowBase + r;
        float zr[DL];
        #pragma unroll
        for (int k=0;k<DL;k++) zr[k] = zs[r][k];
        pm_oct(zr, cs, ms, o);
        if (o == 0) z_store(zr, row);
        h_update4(zr, wps, bps, row, o*4, make_float4(0.f,0.f,0.f,0.f));
    }
}

// ---------- lateral: HMMA dot -> K in regs -> HMMA K@H; cp.async double-buffer ----------
__global__ __launch_bounds__(256,4) void lateral_mma_kernel()
{
    __shared__ __align__(16) char zjs[2][KC*ZJ_ROW];      // 2 x 3 KB
    __shared__ __align__(16) float csq[2][KC];            // 2 x 256 B
    __shared__ __align__(16) char hTs[2][HT_CHUNK];       // 2 x 4.5 KB

    const int tid  = threadIdx.x;
    const int wid  = tid >> 5;
    const int lane = tid & 31;
    const int grp  = lane >> 2;
    const int t    = lane & 3;
    const int i0 = blockIdx.x * ITILE;
    const int jbase = blockIdx.y * JRANGE;

    const int rowa = i0 + wid*16 + grp;
    const int rowb = rowa + 8;
    uint32_t a0 = *(const uint32_t*)&g_zhl[rowa*16 + 2*t];
    uint32_t a1 = *(const uint32_t*)&g_zhl[rowb*16 + 2*t];
    uint32_t a2 = *(const uint32_t*)&g_zhl[rowa*16 + 8 + 2*t];
    uint32_t a3 = *(const uint32_t*)&g_zhl[rowb*16 + 8 + 2*t];
    const float csia = g_sq[rowa];
    const float csib = g_sq[rowb];

    const uint32_t zjB0 = smem_u32(zjs[0]);
    const uint32_t zjB1 = smem_u32(zjs[1]);
    const uint32_t hTB0 = smem_u32(hTs[0]);
    const uint32_t hTB1 = smem_u32(hTs[1]);
    const uint32_t cqB0 = smem_u32(csq[0]);
    const uint32_t cqB1 = smem_u32(csq[1]);

    // stage chunk cc into buffer b (pure async copies)
    #define STAGE(cc, b) do { \
        const int j0g_ = jbase + (cc)*KC; \
        uint32_t zjB_ = (b) ? zjB1 : zjB0; \
        uint32_t hTB_ = (b) ? hTB1 : hTB0; \
        uint32_t cqB_ = (b) ? cqB1 : cqB0; \
        if (tid < 128){ \
            int j_ = tid >> 1, half_ = tid & 1; \
            CP16(zjB_ + j_*ZJ_ROW + half_*16, \
                 (const char*)&g_zhl[(size_t)(j0g_ + j_)*16 + half_*8]); \
        } \
        if (tid < KC) CP4(cqB_ + tid*4, (const char*)&g_sq[j0g_ + tid]); \
        { \
            const char* src_ = g_hT + (size_t)(j0g_ >> 6) * HT_CHUNK; \
            for (int s_ = tid; s_ < HT_CHUNK/16; s_ += 256) \
                CP16(hTB_ + s_*16, src_ + s_*16); \
        } \
    } while(0)

    float hacc[4][4];
    #pragma unroll
    for (int n=0;n<4;n++)
        #pragma unroll
        for (int r=0;r<4;r++) hacc[n][r] = 0.f;

    STAGE(0, 0);
    CPCOMMIT();

    for (int c = 0; c < NCH; c++){
        CPWAIT0();
        __syncthreads();
        if (c + 1 < NCH){
            STAGE(c+1, (c+1)&1);
            CPCOMMIT();
        }
        const uint32_t zjB = (c & 1) ? zjB1 : zjB0;
        const uint32_t hTB = (c & 1) ? hTB1 : hTB0;
        const float* cq = csq[c & 1];

        #pragma unroll
        for (int ks = 0; ks < 4; ks++){
            uint32_t ka[4];
            #pragma unroll
            for (int g = 0; g < 2; g++){
                float cc0=0.f, cc1=0.f, cc2=0.f, cc3=0.f;
                int j = ks*16 + g*8 + grp;
                uint32_t b0, b1;
                LDS32(b0, zjB + j*ZJ_ROW + 4*t);
                LDS32(b1, zjB + j*ZJ_ROW + 16 + 4*t);
                MMA16816(cc0,cc1,cc2,cc3, a0,a1,a2,a3, b0,b1);   // hi.hi + lo.lo
                MMA16816(cc0,cc1,cc2,cc3, a0,a1,a2,a3, b1,b0);   // hi.lo + lo.hi
                float2 sj = *(const float2*)&cq[ks*16 + g*8 + 2*t];
                float ea0 = fmaf(M2CI_F, cc0, csia + sj.x);
                float ea1 = fmaf(M2CI_F, cc1, csia + sj.y);
                float ea2 = fmaf(M2CI_F, cc2, csib + sj.x);
                float ea3 = fmaf(M2CI_F, cc3, csib + sj.y);
                float e0 = ex2f(ea0), e1 = ex2f(ea1), e2 = ex2f(ea2), e3 = ex2f(ea3);
                float p0 = e0*e0, p1 = e1*e1, p2 = e2*e2, p3 = e3*e3;
                float K0 = fmaf(0.8f, p0*p0, -e0);
                float K1 = fmaf(0.8f, p1*p1, -e1);
                float K2 = fmaf(0.8f, p2*p2, -e2);
                float K3 = fmaf(0.8f, p3*p3, -e3);
                CVT_BF2(ka[g*2+0], K1, K0);
                CVT_BF2(ka[g*2+1], K3, K2);
            }
            #pragma unroll
            for (int n = 0; n < 4; n++){
                uint32_t hb0, hb1;
                uint32_t haddr = hTB + (n*8 + grp)*HT_ROW + (ks*16 + 2*t)*2;
                LDS32(hb0, haddr);
                LDS32(hb1, haddr + 16);
                MMA16816(hacc[n][0],hacc[n][1],hacc[n][2],hacc[n][3],
                         ka[0],ka[1],ka[2],ka[3], hb0, hb1);
            }
        }
    }
    #undef STAGE

    {
        float* d0 = &g_part[((size_t)blockIdx.y*NB + rowa)*CH];
        float* d1 = &g_part[((size_t)blockIdx.y*NB + rowb)*CH];
        #pragma unroll
        for (int n = 0; n < 4; n++){
            *(float2*)&d0[n*8 + 2*t] = make_float2(hacc[n][0], hacc[n][1]);
            *(float2*)&d1[n*8 + 2*t] = make_float2(hacc[n][2], hacc[n][3]);
        }
    }
}

// ------- fused: hcomb = hpre + 0.05*sum(part); z = pm(z); h/hT update -------
__global__ __launch_bounds__(128) void fused_kernel(
    const float* __restrict__ centers, const float* __restrict__ mus,
    const float* __restrict__ Wp, const float* __restrict__ bp)
{
    __shared__ float cs[NC*DL];
    __shared__ float ms[NC];
    __shared__ float wps[DL*CH];
    __shared__ float bps[CH];
    const int tid = threadIdx.x;
    if (tid < NC*DL) cs[tid] = centers[tid];
    if (tid < NC) ms[tid] = mus[tid];
    for (int t = tid; t < DL*CH; t += 128) wps[t] = Wp[t];
    if (tid < CH) bps[tid] = bp[tid];
    __syncthreads();

    const int row = blockIdx.x*16 + (tid >> 3);
    const int o   = tid & 7;
    const int c0  = o*4;

    float tx=0.f, ty=0.f, tz=0.f, tw=0.f;
    #pragma unroll
    for (int c=0;c<NCHUNK;c++){
        float4 p = *(const float4*)&g_part[((size_t)c*NB + row)*CH + c0];
        tx+=p.x; ty+=p.y; tz+=p.z; tw+=p.w;
    }
    float4 h0 = *(const float4*)&g_hpre[(size_t)row*CH + c0];
    float4 hc;
    hc.x = fmaf(0.05f, tx, h0.x);
    hc.y = fmaf(0.05f, ty, h0.y);
    hc.z = fmaf(0.05f, tz, h0.z);
    hc.w = fmaf(0.05f, tw, h0.w);

    float zr[DL];
    {
        float4 a = *(const float4*)&g_z[row*DL];
        float4 b = *(const float4*)&g_z[row*DL+4];
        zr[0]=a.x; zr[1]=a.y; zr[2]=a.z; zr[3]=a.w;
        zr[4]=b.x; zr[5]=b.y; zr[6]=b.z; zr[7]=b.w;
    }
    pm_oct(zr, cs, ms, o);
    if (o == 0) z_store(zr, row);
    h_update4(zr, wps, bps, row, c0, hc);
}

// ------- final: hcomb = hpre + 0.05*sum(part); y = hcomb @ Wr + br -------
__global__ __launch_bounds__(128) void final_kernel(
    const float* __restrict__ Wr, const float* __restrict__ br,
    float* __restrict__ y)
{
    __shared__ float wrs[CH*DOUT];
    __shared__ float brs[DOUT];
    const int tid = threadIdx.x;
    for (int t=tid; t<CH*DOUT; t+=128) wrs[t] = Wr[t];
    if (tid < DOUT) brs[tid] = br[tid];
    __syncthreads();

    const int row = blockIdx.x*32 + (tid >> 2);
    const int q   = tid & 3;
    const int c0  = q*8;

    float t0x=0.f,t0y=0.f,t0z=0.f,t0w=0.f, t1x=0.f,t1y=0.f,t1z=0.f,t1w=0.f;
    #pragma unroll
    for (int c=0;c<NCHUNK;c++){
        const float* base = &g_part[((size_t)c*NB + row)*CH + c0];
        float4 p0 = *(const float4*)base;
        float4 p1 = *(const float4*)(base+4);
        t0x+=p0.x; t0y+=p0.y; t0z+=p0.z; t0w+=p0.w;
        t1x+=p1.x; t1y+=p1.y; t1z+=p1.z; t1w+=p1.w;
    }
    float4 h0 = *(const float4*)&g_hpre[(size_t)row*CH + c0];
    float4 h1 = *(const float4*)&g_hpre[(size_t)row*CH + c0 + 4];
    float hc[8];
    hc[0] = fmaf(0.05f, t0x, h0.x); hc[1] = fmaf(0.05f, t0y, h0.y);
    hc[2] = fmaf(0.05f, t0z, h0.z); hc[3] = fmaf(0.05f, t0w, h0.w);
    hc[4] = fmaf(0.05f, t1x, h1.x); hc[5] = fmaf(0.05f, t1y, h1.y);
    hc[6] = fmaf(0.05f, t1z, h1.z); hc[7] = fmaf(0.05f, t1w, h1.w);

    float o[DOUT];
    #pragma unroll
    for (int d=0; d<DOUT; d++) o[d] = 0.f;
    #pragma unroll
    for (int u=0;u<8;u++){
        float hcu = hc[u];
        #pragma unroll
        for (int d=0; d<DOUT; d++) o[d] = fmaf(hcu, wrs[(c0+u)*DOUT+d], o[d]);
    }
    #pragma unroll
    for (int off=1; off<4; off<<=1){
        #pragma unroll
        for (int d=0; d<DOUT; d++) o[d] += __shfl_xor_sync(0xffffffffu, o[d], off);
    }
    if (q == 0){
        #pragma unroll
        for (int d=0; d<DOUT; d++) y[(size_t)row*DOUT + d] = o[d] + brs[d];
    }
}

// ---------------- launch ----------------
extern "C" void kernel_launch(void* const* d_in, const int* in_sizes, int n_in,
                              void* d_out, int out_size)
{
    const float* x       = (const float*)d_in[0];
    const float* W1      = (const float*)d_in[1];
    const float* b1      = (const float*)d_in[2];
    const float* W2      = (const float*)d_in[3];
    const float* b2      = (const float*)d_in[4];
    const float* centers = (const float*)d_in[5];
    const float* mus     = (const float*)d_in[6];
    const float* Wp      = (const float*)d_in[7];
    const float* bp      = (const float*)d_in[8];
    const float* Wr      = (const float*)d_in[9];
    const float* br      = (const float*)d_in[10];
    float* y = (float*)d_out;

    enc_kernel<<<NB/16, 256>>>(x, W1, b1, W2, b2, centers, mus, Wp, bp);
    for (int t = 1; t <= TSTEPS; t++){
        lateral_mma_kernel<<<dim3(NB/ITILE, NJS), 256>>>();
        if (t < TSTEPS)
            fused_kernel<<<NB/16, 128>>>(centers, mus, Wp, bp);
    }
    final_kernel<<<NB/32, 128>>>(Wr, br, y);
}

// round 14
// speedup vs baseline: 1.2329x; 1.2329x over previous
#include <cuda_runtime.h>
#include <cuda_bf16.h>
#include <cstdint>

#define NB   4096
#define DIN  784
#define NH   128
#define DL   8
#define NC   16
#define CH   32
#define DOUT 10
#define NCHUNK 16
#define TSTEPS 5

// lateral tiling
#define ITILE 128
#define KC    64
#define NJS   16
#define JRANGE (NB/NJS)     // 256
#define NCH   (JRANGE/KC)   // 4

#define HT_ROW 144              // 72 bf16 per hT row (padded, conflict-free LDS)
#define HT_CHUNK (CH*HT_ROW)    // 4608 B per 64-j chunk
#define ZJ_ROW 48               // 24 bf16 per zj row (16 used)

// ---------------- scratch ----------------
__device__ __align__(16) float g_z[NB*DL];
__device__ float g_sq[NB];                       // CI * |z|^2
__device__ __align__(16) __nv_bfloat16 g_zhl[NB*16];   // [hi0..hi7, lo0..lo7]
__device__ __align__(16) float g_hpre[NB*CH];
__device__ __align__(16) char  g_hT[(NB/KC)*HT_CHUNK]; // bf16 [chunk][ch][72]
__device__ __align__(16) float g_part[(size_t)NCHUNK*NB*CH];

// ---------------- math helpers ----------
__device__ __forceinline__ float ex2f(float x){
    float y; asm("ex2.approx.f32 %0, %1;" : "=f"(y) : "f"(x)); return y;
}
__device__ __forceinline__ float rcp_acc(float x){
    float r; asm("rcp.approx.f32 %0, %1;" : "=f"(r) : "f"(x));
    return r * fmaf(-x, r, 2.0f);
}
__device__ __forceinline__ float rsqrt_acc(float x){
    float r; asm("rsqrt.approx.f32 %0, %1;" : "=f"(r) : "f"(x));
    float e = x * r;
    return r * fmaf(-0.5f, e * r, 1.5f);
}
__device__ __forceinline__ float tanh_acc(float x){
    float ax = fabsf(x);
    float t  = ex2f(-2.8853900817779268f * ax);
    float y  = (1.0f - t) * rcp_acc(1.0f + t);
    return copysignf(y, x);
}

#define CI_F   (-0.50093577808644655f)
#define M2CI_F ( 1.0018715561728931f)

__device__ __forceinline__ uint32_t smem_u32(const void* p){
    uint32_t a;
    asm("{ .reg .u64 t; cvta.to.shared.u64 t, %1; cvt.u32.u64 %0, t; }" : "=r"(a) : "l"(p));
    return a;
}
#define MMA16816(c0,c1,c2,c3,a0,a1,a2,a3,b0,b1) \
    asm volatile("mma.sync.aligned.m16n8k16.row.col.f32.bf16.bf16.f32 " \
        "{%0,%1,%2,%3}, {%4,%5,%6,%7}, {%8,%9}, {%0,%1,%2,%3};" \
        : "+f"(c0),"+f"(c1),"+f"(c2),"+f"(c3) \
        : "r"(a0),"r"(a1),"r"(a2),"r"(a3),"r"(b0),"r"(b1))
#define CVT_BF2(d,hi,lo) asm("cvt.rn.satfinite.bf16x2.f32 %0, %1, %2;" : "=r"(d) : "f"(hi), "f"(lo))
#define LDS32(d, addr) asm volatile("ld.shared.b32 %0, [%1];" : "=r"(d) : "r"(addr))
#define CP16(dst, src) asm volatile("cp.async.cg.shared.global [%0], [%1], 16;" :: "r"(dst), "l"(src) : "memory")
#define CP4(dst, src)  asm volatile("cp.async.ca.shared.global [%0], [%1], 4;"  :: "r"(dst), "l"(src) : "memory")
#define CPCOMMIT() asm volatile("cp.async.commit_group;" ::: "memory")
#define CPWAIT0()  asm volatile("cp.async.wait_group 0;" ::: "memory")

// ---- pm field (4 steps), 8 threads per row (2 centers each) ----
__device__ __forceinline__ void pm_oct(float zr[DL], const float* cs,
                                       const float* ms, int o)
{
    #pragma unroll
    for (int step=0; step<4; step++){
        float n = 0.f;
        float g[DL] = {0.f,0.f,0.f,0.f,0.f,0.f,0.f,0.f};
        #pragma unroll
        for (int cc=0;cc<2;cc++){
            int c = o*2 + cc;
            float rv[DL]; float r2 = 1e-4f;
            #pragma unroll
            for (int k=0;k<DL;k++){ rv[k] = zr[k]-cs[c*DL+k]; r2 = fmaf(rv[k],rv[k],r2); }
            float rinv = rsqrt_acc(r2);
            float mr = ms[c]*rinv;
            n += mr;
            float w = mr*rinv*rinv;
            #pragma unroll
            for (int k=0;k<DL;k++) g[k] = fmaf(-w, rv[k], g[k]);
        }
        #pragma unroll
        for (int off=1; off<8; off<<=1){
            n += __shfl_xor_sync(0xffffffffu, n, off);
            #pragma unroll
            for (int k=0;k<DL;k++) g[k] += __shfl_xor_sync(0xffffffffu, g[k], off);
        }
        float s = 0.15f * rcp_acc(n + 1.0f);
        #pragma unroll
        for (int k=0;k<DL;k++)
            zr[k] = fminf(fmaxf(fmaf(s, g[k], zr[k]), -3.f), 3.f);
    }
}

__device__ __forceinline__ void z_store(const float zr[DL], int row)
{
    float s2 = 0.f;
    #pragma unroll
    for (int k=0;k<DL;k++) s2 = fmaf(zr[k], zr[k], s2);
    g_sq[row] = CI_F * s2;
    *(float4*)&g_z[row*DL]   = make_float4(zr[0],zr[1],zr[2],zr[3]);
    *(float4*)&g_z[row*DL+4] = make_float4(zr[4],zr[5],zr[6],zr[7]);
    __nv_bfloat16 hi[8], lo[8];
    #pragma unroll
    for (int k=0;k<DL;k++){
        hi[k] = __float2bfloat16(zr[k]);
        lo[k] = __float2bfloat16(zr[k] - __bfloat162float(hi[k]));
    }
    __nv_bfloat16* dst = &g_zhl[row*16];
    *(uint4*)dst       = *(uint4*)hi;
    *(uint4*)(dst + 8) = *(uint4*)lo;
}

__device__ __forceinline__ void h_update4(const float zr[DL], const float* wps,
                                          const float* bps, int row, int c0,
                                          float4 hc)
{
    float a4[4];
    #pragma unroll
    for (int u=0;u<4;u++) a4[u] = bps[c0+u];
    #pragma unroll
    for (int k=0;k<DL;k++){
        float zk = zr[k];
        #pragma unroll
        for (int u=0;u<4;u++) a4[u] = fmaf(zk, wps[k*CH + c0 + u], a4[u]);
    }
    float4 hv;
    hv.x = fmaf(0.9f, hc.x, 0.1f*tanh_acc(a4[0]));
    hv.y = fmaf(0.9f, hc.y, 0.1f*tanh_acc(a4[1]));
    hv.z = fmaf(0.9f, hc.z, 0.1f*tanh_acc(a4[2]));
    hv.w = fmaf(0.9f, hc.w, 0.1f*tanh_acc(a4[3]));
    *(float4*)&g_hpre[(size_t)row*CH + c0] = hv;
    int jl = row & 63;
    char* base = g_hT + (size_t)(row >> 6) * HT_CHUNK + jl*2;
    *(__nv_bfloat16*)(base + (c0+0)*HT_ROW) = __float2bfloat16(hv.x);
    *(__nv_bfloat16*)(base + (c0+1)*HT_ROW) = __float2bfloat16(hv.y);
    *(__nv_bfloat16*)(base + (c0+2)*HT_ROW) = __float2bfloat16(hv.z);
    *(__nv_bfloat16*)(base + (c0+3)*HT_ROW) = __float2bfloat16(hv.w);
}

// ---------------- encoder (R10: 32 rows/CTA) + fused prep tail ----------------
__global__ __launch_bounds__(256) void enc_kernel(
    const float* __restrict__ x, const float* __restrict__ W1,
    const float* __restrict__ b1, const float* __restrict__ W2,
    const float* __restrict__ b2,
    const float* __restrict__ centers, const float* __restrict__ mus,
    const float* __restrict__ Wp, const float* __restrict__ bp)
{
    __shared__ float xs[32][33];
    __shared__ __align__(16) float ws[32][NH];
    __shared__ float hs[32][NH+1];
    __shared__ float w2s[NH*DL];
    __shared__ float cs[NC*DL];
    __shared__ float ms[NC];
    __shared__ float wps[DL*CH];
    __shared__ float bps[CH];

    const int tid = threadIdx.x;
    const int rowBase = blockIdx.x * 32;
    const int rg = tid >> 4;
    const int cg = tid & 15;

    for (int t = tid; t < NH*DL; t += 256) w2s[t] = W2[t];
    if (tid < NC*DL) cs[tid] = centers[tid];
    if (tid < NC) ms[tid] = mus[tid];
    for (int t = tid; t < DL*CH; t += 256) wps[t] = Wp[t];
    if (tid < CH) bps[tid] = bp[tid];

    float acc[2][8];
    #pragma unroll
    for (int a=0;a<2;a++)
        #pragma unroll
        for (int u=0;u<8;u++) acc[a][u]=0.f;

    for (int k0 = 0; k0 < DIN; k0 += 32) {
        for (int t = tid; t < 32*32; t += 256) {
            int r = t >> 5, k = t & 31;
            int kk = k0 + k;
            xs[r][k] = (kk < DIN) ? x[(size_t)(rowBase + r)*DIN + kk] : 0.f;
        }
        for (int t = tid; t < 32*NH; t += 256) {
            int k = t >> 7, c = t & (NH-1);
            int kk = k0 + k;
            ws[k][c] = (kk < DIN) ? W1[(size_t)kk*NH + c] : 0.f;
        }
        __syncthreads();
        #pragma unroll
        for (int kk = 0; kk < 32; kk++) {
            float x0 = xs[rg*2+0][kk];
            float x1 = xs[rg*2+1][kk];
            float4 w0 = *(const float4*)&ws[kk][cg*8];
            float4 w1 = *(const float4*)&ws[kk][cg*8+4];
            acc[0][0] = fmaf(x0, w0.x, acc[0][0]);
            acc[0][1] = fmaf(x0, w0.y, acc[0][1]);
            acc[0][2] = fmaf(x0, w0.z, acc[0][2]);
            acc[0][3] = fmaf(x0, w0.w, acc[0][3]);
            acc[0][4] = fmaf(x0, w1.x, acc[0][4]);
            acc[0][5] = fmaf(x0, w1.y, acc[0][5]);
            acc[0][6] = fmaf(x0, w1.z, acc[0][6]);
            acc[0][7] = fmaf(x0, w1.w, acc[0][7]);
            acc[1][0] = fmaf(x1, w0.x, acc[1][0]);
            acc[1][1] = fmaf(x1, w0.y, acc[1][1]);
            acc[1][2] = fmaf(x1, w0.z, acc[1][2]);
            acc[1][3] = fmaf(x1, w0.w, acc[1][3]);
            acc[1][4] = fmaf(x1, w1.x, acc[1][4]);
            acc[1][5] = fmaf(x1, w1.y, acc[1][5]);
            acc[1][6] = fmaf(x1, w1.z, acc[1][6]);
            acc[1][7] = fmaf(x1, w1.w, acc[1][7]);
        }
        __syncthreads();
    }
    #pragma unroll
    for (int a=0;a<2;a++){
        int r = rg*2+a;
        #pragma unroll
        for (int u=0;u<8;u++){
            int c = cg*8+u;
            hs[r][c] = tanh_acc(acc[a][u] + b1[c]);
        }
    }
    __syncthreads();
    {
        int r = tid >> 3;
        int o = tid & 7;
        float s = b2[o];
        #pragma unroll 16
        for (int k=0;k<NH;k++) s = fmaf(hs[r][k], w2s[k*DL+o], s);
        xs[r][o] = s;                  // stage z block-locally (reuse xs)
    }
    __syncthreads();

    // ---- fused prep tail: pm(z), side-products, hpre (h = 0) ----
    {
        const int r = tid >> 3;
        const int o = tid & 7;
        const int row = rowBase + r;
        float zr[DL];
        #pragma unroll
        for (int k=0;k<DL;k++) zr[k] = xs[r][k];
        pm_oct(zr, cs, ms, o);
        if (o == 0) z_store(zr, row);
        h_update4(zr, wps, bps, row, o*4, make_float4(0.f,0.f,0.f,0.f));
    }
}

// ---------- lateral: HMMA dot -> K in regs -> HMMA K@H; cp.async double-buffer ----------
__global__ __launch_bounds__(256,4) void lateral_mma_kernel()
{
    __shared__ __align__(16) char zjs[2][KC*ZJ_ROW];      // 2 x 3 KB
    __shared__ __align__(16) float csq[2][KC];            // 2 x 256 B
    __shared__ __align__(16) char hTs[2][HT_CHUNK];       // 2 x 4.5 KB

    const int tid  = threadIdx.x;
    const int wid  = tid >> 5;
    const int lane = tid & 31;
    const int grp  = lane >> 2;
    const int t    = lane & 3;
    const int i0 = blockIdx.x * ITILE;
    const int jbase = blockIdx.y * JRANGE;

    const int rowa = i0 + wid*16 + grp;
    const int rowb = rowa + 8;
    uint32_t a0 = *(const uint32_t*)&g_zhl[rowa*16 + 2*t];
    uint32_t a1 = *(const uint32_t*)&g_zhl[rowb*16 + 2*t];
    uint32_t a2 = *(const uint32_t*)&g_zhl[rowa*16 + 8 + 2*t];
    uint32_t a3 = *(const uint32_t*)&g_zhl[rowb*16 + 8 + 2*t];
    const float csia = g_sq[rowa];
    const float csib = g_sq[rowb];

    const uint32_t zjB0 = smem_u32(zjs[0]);
    const uint32_t zjB1 = smem_u32(zjs[1]);
    const uint32_t hTB0 = smem_u32(hTs[0]);
    const uint32_t hTB1 = smem_u32(hTs[1]);
    const uint32_t cqB0 = smem_u32(csq[0]);
    const uint32_t cqB1 = smem_u32(csq[1]);

    #define STAGE(cc, b) do { \
        const int j0g_ = jbase + (cc)*KC; \
        uint32_t zjB_ = (b) ? zjB1 : zjB0; \
        uint32_t hTB_ = (b) ? hTB1 : hTB0; \
        uint32_t cqB_ = (b) ? cqB1 : cqB0; \
        if (tid < 128){ \
            int j_ = tid >> 1, half_ = tid & 1; \
            CP16(zjB_ + j_*ZJ_ROW + half_*16, \
                 (const char*)&g_zhl[(size_t)(j0g_ + j_)*16 + half_*8]); \
        } \
        if (tid < KC) CP4(cqB_ + tid*4, (const char*)&g_sq[j0g_ + tid]); \
        { \
            const char* src_ = g_hT + (size_t)(j0g_ >> 6) * HT_CHUNK; \
            for (int s_ = tid; s_ < HT_CHUNK/16; s_ += 256) \
                CP16(hTB_ + s_*16, src_ + s_*16); \
        } \
    } while(0)

    float hacc[4][4];
    #pragma unroll
    for (int n=0;n<4;n++)
        #pragma unroll
        for (int r=0;r<4;r++) hacc[n][r] = 0.f;

    STAGE(0, 0);
    CPCOMMIT();

    for (int c = 0; c < NCH; c++){
        CPWAIT0();
        __syncthreads();
        if (c + 1 < NCH){
            STAGE(c+1, (c+1)&1);
            CPCOMMIT();
        }
        const uint32_t zjB = (c & 1) ? zjB1 : zjB0;
        const uint32_t hTB = (c & 1) ? hTB1 : hTB0;
        const float* cq = csq[c & 1];

        #pragma unroll
        for (int ks = 0; ks < 4; ks++){
            uint32_t ka[4];
            #pragma unroll
            for (int g = 0; g < 2; g++){
                float cc0=0.f, cc1=0.f, cc2=0.f, cc3=0.f;
                int j = ks*16 + g*8 + grp;
                uint32_t b0, b1;
                LDS32(b0, zjB + j*ZJ_ROW + 4*t);
                LDS32(b1, zjB + j*ZJ_ROW + 16 + 4*t);
                MMA16816(cc0,cc1,cc2,cc3, a0,a1,a2,a3, b0,b1);   // hi.hi + lo.lo
                MMA16816(cc0,cc1,cc2,cc3, a0,a1,a2,a3, b1,b0);   // hi.lo + lo.hi
                float2 sj = *(const float2*)&cq[ks*16 + g*8 + 2*t];
                float ea0 = fmaf(M2CI_F, cc0, csia + sj.x);
                float ea1 = fmaf(M2CI_F, cc1, csia + sj.y);
                float ea2 = fmaf(M2CI_F, cc2, csib + sj.x);
                float ea3 = fmaf(M2CI_F, cc3, csib + sj.y);
                float e0 = ex2f(ea0), e1 = ex2f(ea1), e2 = ex2f(ea2), e3 = ex2f(ea3);
                float p0 = e0*e0, p1 = e1*e1, p2 = e2*e2, p3 = e3*e3;
                float K0 = fmaf(0.8f, p0*p0, -e0);
                float K1 = fmaf(0.8f, p1*p1, -e1);
                float K2 = fmaf(0.8f, p2*p2, -e2);
                float K3 = fmaf(0.8f, p3*p3, -e3);
                CVT_BF2(ka[g*2+0], K1, K0);
                CVT_BF2(ka[g*2+1], K3, K2);
            }
            #pragma unroll
            for (int n = 0; n < 4; n++){
                uint32_t hb0, hb1;
                uint32_t haddr = hTB + (n*8 + grp)*HT_ROW + (ks*16 + 2*t)*2;
                LDS32(hb0, haddr);
                LDS32(hb1, haddr + 16);
                MMA16816(hacc[n][0],hacc[n][1],hacc[n][2],hacc[n][3],
                         ka[0],ka[1],ka[2],ka[3], hb0, hb1);
            }
        }
    }
    #undef STAGE

    {
        float* d0 = &g_part[((size_t)blockIdx.y*NB + rowa)*CH];
        float* d1 = &g_part[((size_t)blockIdx.y*NB + rowb)*CH];
        #pragma unroll
        for (int n = 0; n < 4; n++){
            *(float2*)&d0[n*8 + 2*t] = make_float2(hacc[n][0], hacc[n][1]);
            *(float2*)&d1[n*8 + 2*t] = make_float2(hacc[n][2], hacc[n][3]);
        }
    }
}

// ------- fused: hcomb = hpre + 0.05*sum(part); z = pm(z); h/hT update -------
__global__ __launch_bounds__(128) void fused_kernel(
    const float* __restrict__ centers, const float* __restrict__ mus,
    const float* __restrict__ Wp, const float* __restrict__ bp)
{
    __shared__ float cs[NC*DL];
    __shared__ float ms[NC];
    __shared__ float wps[DL*CH];
    __shared__ float bps[CH];
    const int tid = threadIdx.x;
    if (tid < NC*DL) cs[tid] = centers[tid];
    if (tid < NC) ms[tid] = mus[tid];
    for (int t = tid; t < DL*CH; t += 128) wps[t] = Wp[t];
    if (tid < CH) bps[tid] = bp[tid];
    __syncthreads();

    const int row = blockIdx.x*16 + (tid >> 3);
    const int o   = tid & 7;
    const int c0  = o*4;

    float tx=0.f, ty=0.f, tz=0.f, tw=0.f;
    #pragma unroll
    for (int c=0;c<NCHUNK;c++){
        float4 p = *(const float4*)&g_part[((size_t)c*NB + row)*CH + c0];
        tx+=p.x; ty+=p.y; tz+=p.z; tw+=p.w;
    }
    float4 h0 = *(const float4*)&g_hpre[(size_t)row*CH + c0];
    float4 hc;
    hc.x = fmaf(0.05f, tx, h0.x);
    hc.y = fmaf(0.05f, ty, h0.y);
    hc.z = fmaf(0.05f, tz, h0.z);
    hc.w = fmaf(0.05f, tw, h0.w);

    float zr[DL];
    {
        float4 a = *(const float4*)&g_z[row*DL];
        float4 b = *(const float4*)&g_z[row*DL+4];
        zr[0]=a.x; zr[1]=a.y; zr[2]=a.z; zr[3]=a.w;
        zr[4]=b.x; zr[5]=b.y; zr[6]=b.z; zr[7]=b.w;
    }
    pm_oct(zr, cs, ms, o);
    if (o == 0) z_store(zr, row);
    h_update4(zr, wps, bps, row, c0, hc);
}

// ------- final: hcomb = hpre + 0.05*sum(part); y = hcomb @ Wr + br -------
__global__ __launch_bounds__(128) void final_kernel(
    const float* __restrict__ Wr, const float* __restrict__ br,
    float* __restrict__ y)
{
    __shared__ float wrs[CH*DOUT];
    __shared__ float brs[DOUT];
    const int tid = threadIdx.x;
    for (int t=tid; t<CH*DOUT; t+=128) wrs[t] = Wr[t];
    if (tid < DOUT) brs[tid] = br[tid];
    __syncthreads();

    const int row = blockIdx.x*32 + (tid >> 2);
    const int q   = tid & 3;
    const int c0  = q*8;

    float t0x=0.f,t0y=0.f,t0z=0.f,t0w=0.f, t1x=0.f,t1y=0.f,t1z=0.f,t1w=0.f;
    #pragma unroll
    for (int c=0;c<NCHUNK;c++){
        const float* base = &g_part[((size_t)c*NB + row)*CH + c0];
        float4 p0 = *(const float4*)base;
        float4 p1 = *(const float4*)(base+4);
        t0x+=p0.x; t0y+=p0.y; t0z+=p0.z; t0w+=p0.w;
        t1x+=p1.x; t1y+=p1.y; t1z+=p1.z; t1w+=p1.w;
    }
    float4 h0 = *(const float4*)&g_hpre[(size_t)row*CH + c0];
    float4 h1 = *(const float4*)&g_hpre[(size_t)row*CH + c0 + 4];
    float hc[8];
    hc[0] = fmaf(0.05f, t0x, h0.x); hc[1] = fmaf(0.05f, t0y, h0.y);
    hc[2] = fmaf(0.05f, t0z, h0.z); hc[3] = fmaf(0.05f, t0w, h0.w);
    hc[4] = fmaf(0.05f, t1x, h1.x); hc[5] = fmaf(0.05f, t1y, h1.y);
    hc[6] = fmaf(0.05f, t1z, h1.z); hc[7] = fmaf(0.05f, t1w, h1.w);

    float o[DOUT];
    #pragma unroll
    for (int d=0; d<DOUT; d++) o[d] = 0.f;
    #pragma unroll
    for (int u=0;u<8;u++){
        float hcu = hc[u];
        #pragma unroll
        for (int d=0; d<DOUT; d++) o[d] = fmaf(hcu, wrs[(c0+u)*DOUT+d], o[d]);
    }
    #pragma unroll
    for (int off=1; off<4; off<<=1){
        #pragma unroll
        for (int d=0; d<DOUT; d++) o[d] += __shfl_xor_sync(0xffffffffu, o[d], off);
    }
    if (q == 0){
        #pragma unroll
        for (int d=0; d<DOUT; d++) y[(size_t)row*DOUT + d] = o[d] + brs[d];
    }
}

// ---------------- launch ----------------
extern "C" void kernel_launch(void* const* d_in, const int* in_sizes, int n_in,
                              void* d_out, int out_size)
{
    const float* x       = (const float*)d_in[0];
    const float* W1      = (const float*)d_in[1];
    const float* b1      = (const float*)d_in[2];
    const float* W2      = (const float*)d_in[3];
    const float* b2      = (const float*)d_in[4];
    const float* centers = (const float*)d_in[5];
    const float* mus     = (const float*)d_in[6];
    const float* Wp      = (const float*)d_in[7];
    const float* bp      = (const float*)d_in[8];
    const float* Wr      = (const float*)d_in[9];
    const float* br      = (const float*)d_in[10];
    float* y = (float*)d_out;

    enc_kernel<<<NB/32, 256>>>(x, W1, b1, W2, b2, centers, mus, Wp, bp);
    for (int t = 1; t <= TSTEPS; t++){
        lateral_mma_kernel<<<dim3(NB/ITILE, NJS), 256>>>();
        if (t < TSTEPS)
            fused_kernel<<<NB/16, 128>>>(centers, mus, Wp, bp);
    }
    final_kernel<<<NB/32, 128>>>(Wr, br, y);
}

// round 16
// speedup vs baseline: 1.5263x; 1.2380x over previous
#include <cuda_runtime.h>
#include <cuda_bf16.h>
#include <cstdint>

#define NB   4096
#define DIN  784
#define NH   128
#define DL   8
#define NC   16
#define CH   32
#define DOUT 10
#define NCHUNK 8
#define TSTEPS 5

// lateral tiling
#define ITILE 128
#define KC    64
#define NJS   8
#define JRANGE (NB/NJS)     // 512
#define NCH   (JRANGE/KC)   // 8

#define HT_ROW 144              // 72 bf16 per hT row (padded, conflict-free LDS)
#define HT_CHUNK (CH*HT_ROW)    // 4608 B per 64-j chunk
#define ZJ_ROW 48               // 24 bf16 per zj row (16 used)

// ---------------- scratch ----------------
__device__ __align__(16) float g_z[NB*DL];
__device__ float g_sq[NB];                       // CI * |z|^2
__device__ __align__(16) __nv_bfloat16 g_zhl[NB*16];   // [hi0..hi7, lo0..lo7]
__device__ __align__(16) float g_hpre[NB*CH];
__device__ __align__(16) char  g_hT[(NB/KC)*HT_CHUNK]; // bf16 [chunk][ch][72]
__device__ __align__(16) float g_part[(size_t)NCHUNK*NB*CH];

// ---------------- math helpers ----------
__device__ __forceinline__ float ex2f(float x){
    float y; asm("ex2.approx.f32 %0, %1;" : "=f"(y) : "f"(x)); return y;
}
__device__ __forceinline__ float rcp_acc(float x){
    float r; asm("rcp.approx.f32 %0, %1;" : "=f"(r) : "f"(x));
    return r * fmaf(-x, r, 2.0f);
}
__device__ __forceinline__ float rsqrt_acc(float x){
    float r; asm("rsqrt.approx.f32 %0, %1;" : "=f"(r) : "f"(x));
    float e = x * r;
    return r * fmaf(-0.5f, e * r, 1.5f);
}
__device__ __forceinline__ float tanh_acc(float x){
    float ax = fabsf(x);
    float t  = ex2f(-2.8853900817779268f * ax);
    float y  = (1.0f - t) * rcp_acc(1.0f + t);
    return copysignf(y, x);
}

#define CI_F   (-0.50093577808644655f)
#define M2CI_F ( 1.0018715561728931f)

__device__ __forceinline__ uint32_t smem_u32(const void* p){
    uint32_t a;
    asm("{ .reg .u64 t; cvta.to.shared.u64 t, %1; cvt.u32.u64 %0, t; }" : "=r"(a) : "l"(p));
    return a;
}
#define MMA16816(c0,c1,c2,c3,a0,a1,a2,a3,b0,b1) \
    asm volatile("mma.sync.aligned.m16n8k16.row.col.f32.bf16.bf16.f32 " \
        "{%0,%1,%2,%3}, {%4,%5,%6,%7}, {%8,%9}, {%0,%1,%2,%3};" \
        : "+f"(c0),"+f"(c1),"+f"(c2),"+f"(c3) \
        : "r"(a0),"r"(a1),"r"(a2),"r"(a3),"r"(b0),"r"(b1))
#define CVT_BF2(d,hi,lo) asm("cvt.rn.satfinite.bf16x2.f32 %0, %1, %2;" : "=r"(d) : "f"(hi), "f"(lo))
#define LDS32(d, addr) asm volatile("ld.shared.b32 %0, [%1];" : "=r"(d) : "r"(addr))
#define CP16(dst, src) asm volatile("cp.async.cg.shared.global [%0], [%1], 16;" :: "r"(dst), "l"(src) : "memory")
#define CP4(dst, src)  asm volatile("cp.async.ca.shared.global [%0], [%1], 4;"  :: "r"(dst), "l"(src) : "memory")
#define CPCOMMIT() asm volatile("cp.async.commit_group;" ::: "memory")
#define CPWAIT0()  asm volatile("cp.async.wait_group 0;" ::: "memory")
#define CPWAIT1()  asm volatile("cp.async.wait_group 1;" ::: "memory")

// ---- pm field (4 steps), 8 threads per row (2 centers each) ----
__device__ __forceinline__ void pm_oct(float zr[DL], const float* cs,
                                       const float* ms, int o)
{
    #pragma unroll
    for (int step=0; step<4; step++){
        float n = 0.f;
        float g[DL] = {0.f,0.f,0.f,0.f,0.f,0.f,0.f,0.f};
        #pragma unroll
        for (int cc=0;cc<2;cc++){
            int c = o*2 + cc;
            float rv[DL]; float r2 = 1e-4f;
            #pragma unroll
            for (int k=0;k<DL;k++){ rv[k] = zr[k]-cs[c*DL+k]; r2 = fmaf(rv[k],rv[k],r2); }
            float rinv = rsqrt_acc(r2);
            float mr = ms[c]*rinv;
            n += mr;
            float w = mr*rinv*rinv;
            #pragma unroll
            for (int k=0;k<DL;k++) g[k] = fmaf(-w, rv[k], g[k]);
        }
        #pragma unroll
        for (int off=1; off<8; off<<=1){
            n += __shfl_xor_sync(0xffffffffu, n, off);
            #pragma unroll
            for (int k=0;k<DL;k++) g[k] += __shfl_xor_sync(0xffffffffu, g[k], off);
        }
        float s = 0.15f * rcp_acc(n + 1.0f);
        #pragma unroll
        for (int k=0;k<DL;k++)
            zr[k] = fminf(fmaxf(fmaf(s, g[k], zr[k]), -3.f), 3.f);
    }
}

__device__ __forceinline__ void z_store(const float zr[DL], int row)
{
    float s2 = 0.f;
    #pragma unroll
    for (int k=0;k<DL;k++) s2 = fmaf(zr[k], zr[k], s2);
    g_sq[row] = CI_F * s2;
    *(float4*)&g_z[row*DL]   = make_float4(zr[0],zr[1],zr[2],zr[3]);
    *(float4*)&g_z[row*DL+4] = make_float4(zr[4],zr[5],zr[6],zr[7]);
    __nv_bfloat16 hi[8], lo[8];
    #pragma unroll
    for (int k=0;k<DL;k++){
        hi[k] = __float2bfloat16(zr[k]);
        lo[k] = __float2bfloat16(zr[k] - __bfloat162float(hi[k]));
    }
    __nv_bfloat16* dst = &g_zhl[row*16];
    *(uint4*)dst       = *(uint4*)hi;
    *(uint4*)(dst + 8) = *(uint4*)lo;
}

__device__ __forceinline__ void h_update4(const float zr[DL], const float* wps,
                                          const float* bps, int row, int c0,
                                          float4 hc)
{
    float a4[4];
    #pragma unroll
    for (int u=0;u<4;u++) a4[u] = bps[c0+u];
    #pragma unroll
    for (int k=0;k<DL;k++){
        float zk = zr[k];
        #pragma unroll
        for (int u=0;u<4;u++) a4[u] = fmaf(zk, wps[k*CH + c0 + u], a4[u]);
    }
    float4 hv;
    hv.x = fmaf(0.9f, hc.x, 0.1f*tanh_acc(a4[0]));
    hv.y = fmaf(0.9f, hc.y, 0.1f*tanh_acc(a4[1]));
    hv.z = fmaf(0.9f, hc.z, 0.1f*tanh_acc(a4[2]));
    hv.w = fmaf(0.9f, hc.w, 0.1f*tanh_acc(a4[3]));
    *(float4*)&g_hpre[(size_t)row*CH + c0] = hv;
    int jl = row & 63;
    char* base = g_hT + (size_t)(row >> 6) * HT_CHUNK + jl*2;
    *(__nv_bfloat16*)(base + (c0+0)*HT_ROW) = __float2bfloat16(hv.x);
    *(__nv_bfloat16*)(base + (c0+1)*HT_ROW) = __float2bfloat16(hv.y);
    *(__nv_bfloat16*)(base + (c0+2)*HT_ROW) = __float2bfloat16(hv.z);
    *(__nv_bfloat16*)(base + (c0+3)*HT_ROW) = __float2bfloat16(hv.w);
}

// ------ encoder (32 rows/CTA; W1 via cp.async, x via reg pipeline) + prep tail ------
__global__ __launch_bounds__(256) void enc_kernel(
    const float* __restrict__ x, const float* __restrict__ W1,
    const float* __restrict__ b1, const float* __restrict__ W2,
    const float* __restrict__ b2,
    const float* __restrict__ centers, const float* __restrict__ mus,
    const float* __restrict__ Wp, const float* __restrict__ bp)
{
    __shared__ float xs[2][32][33];
    __shared__ __align__(16) float ws[2][32][NH];
    __shared__ float hs[32][NH+1];
    __shared__ float w2s[NH*DL];
    __shared__ float cs[NC*DL];
    __shared__ float ms[NC];
    __shared__ float wps[DL*CH];
    __shared__ float bps[CH];

    const int tid = threadIdx.x;
    const int rowBase = blockIdx.x * 32;
    const int rg = tid >> 4;
    const int cg = tid & 15;

    for (int t = tid; t < NH*DL; t += 256) w2s[t] = W2[t];
    if (tid < NC*DL) cs[tid] = centers[tid];
    if (tid < NC) ms[tid] = mus[tid];
    for (int t = tid; t < DL*CH; t += 256) wps[t] = Wp[t];
    if (tid < CH) bps[tid] = bp[tid];

    const int xr = tid >> 3, xq = tid & 7;        // x: row, 4-float granule
    const float* xsrcRow = &x[(size_t)(rowBase + xr)*DIN];

    // W1 staging via cp.async (rows of ws are 512B -> always 16B-aligned dst)
    #define W1_STAGE(cc, b) do { \
        const int k0_ = (cc)*32; \
        _Pragma("unroll") \
        for (int p_ = 0; p_ < 4; p_++){ \
            int g_ = tid + p_*256; \
            int k_ = g_ >> 5, c4_ = (g_ & 31)*4; \
            int kk_ = k0_ + k_; \
            int ks_ = kk_ < DIN ? kk_ : (DIN-1); \
            CP16(smem_u32(&ws[b][k_][c4_]), (const char*)&W1[(size_t)ks_*NH + c4_]); \
        } \
    } while(0)
    // out-of-range W1 rows load row DIN-1 (valid memory); they multiply x==0.

    // x load for a chunk into registers (aligned float4 global load)
    #define X_LOAD(cc, v) do { \
        int kk_ = (cc)*32 + xq*4; \
        (v) = make_float4(0.f,0.f,0.f,0.f); \
        if (kk_ < DIN) (v) = *(const float4*)(xsrcRow + kk_); \
    } while(0)
    #define X_STORE(cc, v) do { \
        float* d_ = &xs[(cc)&1][xr][xq*4]; \
        d_[0]=(v).x; d_[1]=(v).y; d_[2]=(v).z; d_[3]=(v).w; \
    } while(0)

    float acc[2][8];
    #pragma unroll
    for (int a=0;a<2;a++)
        #pragma unroll
        for (int u=0;u<8;u++) acc[a][u]=0.f;

    float4 xv;
    X_LOAD(0, xv);
    X_STORE(0, xv);
    W1_STAGE(0, 0);
    CPCOMMIT();

    for (int c = 0; c < 25; c++){
        float4 xnext;
        if (c + 1 < 25){
            X_LOAD(c+1, xnext);           // issue early; consumed after compute
            W1_STAGE(c+1, (c+1)&1);
            CPCOMMIT();
            CPWAIT1();
        } else {
            CPWAIT0();
        }
        __syncthreads();
        const float (*xsb)[33] = xs[c&1];
        const float (*wsb)[NH] = ws[c&1];
        #pragma unroll
        for (int kk = 0; kk < 32; kk++) {
            float x0 = xsb[rg*2+0][kk];
            float x1 = xsb[rg*2+1][kk];
            float4 w0 = *(const float4*)&wsb[kk][cg*8];
            float4 w1 = *(const float4*)&wsb[kk][cg*8+4];
            acc[0][0] = fmaf(x0, w0.x, acc[0][0]);
            acc[0][1] = fmaf(x0, w0.y, acc[0][1]);
            acc[0][2] = fmaf(x0, w0.z, acc[0][2]);
            acc[0][3] = fmaf(x0, w0.w, acc[0][3]);
            acc[0][4] = fmaf(x0, w1.x, acc[0][4]);
            acc[0][5] = fmaf(x0, w1.y, acc[0][5]);
            acc[0][6] = fmaf(x0, w1.z, acc[0][6]);
            acc[0][7] = fmaf(x0, w1.w, acc[0][7]);
            acc[1][0] = fmaf(x1, w0.x, acc[1][0]);
            acc[1][1] = fmaf(x1, w0.y, acc[1][1]);
            acc[1][2] = fmaf(x1, w0.z, acc[1][2]);
            acc[1][3] = fmaf(x1, w0.w, acc[1][3]);
            acc[1][4] = fmaf(x1, w1.x, acc[1][4]);
            acc[1][5] = fmaf(x1, w1.y, acc[1][5]);
            acc[1][6] = fmaf(x1, w1.z, acc[1][6]);
            acc[1][7] = fmaf(x1, w1.w, acc[1][7]);
        }
        if (c + 1 < 25) X_STORE(c+1, xnext);
        __syncthreads();
    }
    #undef W1_STAGE
    #undef X_LOAD
    #undef X_STORE

    #pragma unroll
    for (int a=0;a<2;a++){
        int r = rg*2+a;
        #pragma unroll
        for (int u=0;u<8;u++){
            int c = cg*8+u;
            hs[r][c] = tanh_acc(acc[a][u] + b1[c]);
        }
    }
    __syncthreads();
    {
        int r = tid >> 3;
        int o = tid & 7;
        float s = b2[o];
        #pragma unroll 16
        for (int k=0;k<NH;k++) s = fmaf(hs[r][k], w2s[k*DL+o], s);
        xs[0][r][o] = s;                  // stage z block-locally
    }
    __syncthreads();

    // ---- fused prep tail: pm(z), side-products, hpre (h = 0) ----
    {
        const int r = tid >> 3;
        const int o = tid & 7;
        const int row = rowBase + r;
        float zr[DL];
        #pragma unroll
        for (int k=0;k<DL;k++) zr[k] = xs[0][r][k];
        pm_oct(zr, cs, ms, o);
        if (o == 0) z_store(zr, row);
        h_update4(zr, wps, bps, row, o*4, make_float4(0.f,0.f,0.f,0.f));
    }
}

// ---------- lateral: HMMA dot -> K in regs -> HMMA K@H; cp.async double-buffer ----------
__global__ __launch_bounds__(256,4) void lateral_mma_kernel()
{
    __shared__ __align__(16) char zjs[2][KC*ZJ_ROW];      // 2 x 3 KB
    __shared__ __align__(16) float csq[2][KC];            // 2 x 256 B
    __shared__ __align__(16) char hTs[2][HT_CHUNK];       // 2 x 4.5 KB

    const int tid  = threadIdx.x;
    const int wid  = tid >> 5;
    const int lane = tid & 31;
    const int grp  = lane >> 2;
    const int t    = lane & 3;
    const int i0 = blockIdx.x * ITILE;
    const int jbase = blockIdx.y * JRANGE;

    const int rowa = i0 + wid*16 + grp;
    const int rowb = rowa + 8;
    uint32_t a0 = *(const uint32_t*)&g_zhl[rowa*16 + 2*t];
    uint32_t a1 = *(const uint32_t*)&g_zhl[rowb*16 + 2*t];
    uint32_t a2 = *(const uint32_t*)&g_zhl[rowa*16 + 8 + 2*t];
    uint32_t a3 = *(const uint32_t*)&g_zhl[rowb*16 + 8 + 2*t];
    const float csia = g_sq[rowa];
    const float csib = g_sq[rowb];

    const uint32_t zjB0 = smem_u32(zjs[0]);
    const uint32_t zjB1 = smem_u32(zjs[1]);
    const uint32_t hTB0 = smem_u32(hTs[0]);
    const uint32_t hTB1 = smem_u32(hTs[1]);
    const uint32_t cqB0 = smem_u32(csq[0]);
    const uint32_t cqB1 = smem_u32(csq[1]);

    #define STAGE(cc, b) do { \
        const int j0g_ = jbase + (cc)*KC; \
        uint32_t zjB_ = (b) ? zjB1 : zjB0; \
        uint32_t hTB_ = (b) ? hTB1 : hTB0; \
        uint32_t cqB_ = (b) ? cqB1 : cqB0; \
        if (tid < 128){ \
            int j_ = tid >> 1, half_ = tid & 1; \
            CP16(zjB_ + j_*ZJ_ROW + half_*16, \
                 (const char*)&g_zhl[(size_t)(j0g_ + j_)*16 + half_*8]); \
        } \
        if (tid < KC) CP4(cqB_ + tid*4, (const char*)&g_sq[j0g_ + tid]); \
        { \
            const char* src_ = g_hT + (size_t)(j0g_ >> 6) * HT_CHUNK; \
            for (int s_ = tid; s_ < HT_CHUNK/16; s_ += 256) \
                CP16(hTB_ + s_*16, src_ + s_*16); \
        } \
    } while(0)

    float hacc[4][4];
    #pragma unroll
    for (int n=0;n<4;n++)
        #pragma unroll
        for (int r=0;r<4;r++) hacc[n][r] = 0.f;

    STAGE(0, 0);
    CPCOMMIT();

    for (int c = 0; c < NCH; c++){
        CPWAIT0();
        __syncthreads();
        if (c + 1 < NCH){
            STAGE(c+1, (c+1)&1);
            CPCOMMIT();
        }
        const uint32_t zjB = (c & 1) ? zjB1 : zjB0;
        const uint32_t hTB = (c & 1) ? hTB1 : hTB0;
        const float* cq = csq[c & 1];

        #pragma unroll
        for (int ks = 0; ks < 4; ks++){
            uint32_t ka[4];
            #pragma unroll
            for (int g = 0; g < 2; g++){
                float cc0=0.f, cc1=0.f, cc2=0.f, cc3=0.f;
                int j = ks*16 + g*8 + grp;
                uint32_t b0, b1;
                LDS32(b0, zjB + j*ZJ_ROW + 4*t);
                LDS32(b1, zjB + j*ZJ_ROW + 16 + 4*t);
                MMA16816(cc0,cc1,cc2,cc3, a0,a1,a2,a3, b0,b1);   // hi.hi + lo.lo
                MMA16816(cc0,cc1,cc2,cc3, a0,a1,a2,a3, b1,b0);   // hi.lo + lo.hi
                float2 sj = *(const float2*)&cq[ks*16 + g*8 + 2*t];
                float ea0 = fmaf(M2CI_F, cc0, csia + sj.x);
                float ea1 = fmaf(M2CI_F, cc1, csia + sj.y);
                float ea2 = fmaf(M2CI_F, cc2, csib + sj.x);
                float ea3 = fmaf(M2CI_F, cc3, csib + sj.y);
                float e0 = ex2f(ea0), e1 = ex2f(ea1), e2 = ex2f(ea2), e3 = ex2f(ea3);
                float p0 = e0*e0, p1 = e1*e1, p2 = e2*e2, p3 = e3*e3;
                float K0 = fmaf(0.8f, p0*p0, -e0);
                float K1 = fmaf(0.8f, p1*p1, -e1);
                float K2 = fmaf(0.8f, p2*p2, -e2);
                float K3 = fmaf(0.8f, p3*p3, -e3);
                CVT_BF2(ka[g*2+0], K1, K0);
                CVT_BF2(ka[g*2+1], K3, K2);
            }
            #pragma unroll
            for (int n = 0; n < 4; n++){
                uint32_t hb0, hb1;
                uint32_t haddr = hTB + (n*8 + grp)*HT_ROW + (ks*16 + 2*t)*2;
                LDS32(hb0, haddr);
                LDS32(hb1, haddr + 16);
                MMA16816(hacc[n][0],hacc[n][1],hacc[n][2],hacc[n][3],
                         ka[0],ka[1],ka[2],ka[3], hb0, hb1);
            }
        }
    }
    #undef STAGE

    {
        float* d0 = &g_part[((size_t)blockIdx.y*NB + rowa)*CH];
        float* d1 = &g_part[((size_t)blockIdx.y*NB + rowb)*CH];
        #pragma unroll
        for (int n = 0; n < 4; n++){
            *(float2*)&d0[n*8 + 2*t] = make_float2(hacc[n][0], hacc[n][1]);
            *(float2*)&d1[n*8 + 2*t] = make_float2(hacc[n][2], hacc[n][3]);
        }
    }
}

// ------- fused: hcomb = hpre + 0.05*sum(part); z = pm(z); h/hT update -------
__global__ __launch_bounds__(128) void fused_kernel(
    const float* __restrict__ centers, const float* __restrict__ mus,
    const float* __restrict__ Wp, const float* __restrict__ bp)
{
    __shared__ float cs[NC*DL];
    __shared__ float ms[NC];
    __shared__ float wps[DL*CH];
    __shared__ float bps[CH];
    const int tid = threadIdx.x;
    if (tid < NC*DL) cs[tid] = centers[tid];
    if (tid < NC) ms[tid] = mus[tid];
    for (int t = tid; t < DL*CH; t += 128) wps[t] = Wp[t];
    if (tid < CH) bps[tid] = bp[tid];
    __syncthreads();

    const int row = blockIdx.x*16 + (tid >> 3);
    const int o   = tid & 7;
    const int c0  = o*4;

    float tx=0.f, ty=0.f, tz=0.f, tw=0.f;
    #pragma unroll
    for (int c=0;c<NCHUNK;c++){
        float4 p = *(const float4*)&g_part[((size_t)c*NB + row)*CH + c0];
        tx+=p.x; ty+=p.y; tz+=p.z; tw+=p.w;
    }
    float4 h0 = *(const float4*)&g_hpre[(size_t)row*CH + c0];
    float4 hc;
    hc.x = fmaf(0.05f, tx, h0.x);
    hc.y = fmaf(0.05f, ty, h0.y);
    hc.z = fmaf(0.05f, tz, h0.z);
    hc.w = fmaf(0.05f, tw, h0.w);

    float zr[DL];
    {
        float4 a = *(const float4*)&g_z[row*DL];
        float4 b = *(const float4*)&g_z[row*DL+4];
        zr[0]=a.x; zr[1]=a.y; zr[2]=a.z; zr[3]=a.w;
        zr[4]=b.x; zr[5]=b.y; zr[6]=b.z; zr[7]=b.w;
    }
    pm_oct(zr, cs, ms, o);
    if (o == 0) z_store(zr, row);
    h_update4(zr, wps, bps, row, c0, hc);
}

// ------- final: hcomb = hpre + 0.05*sum(part); y = hcomb @ Wr + br -------
__global__ __launch_bounds__(128) void final_kernel(
    const float* __restrict__ Wr, const float* __restrict__ br,
    float* __restrict__ y)
{
    __shared__ float wrs[CH*DOUT];
    __shared__ float brs[DOUT];
    const int tid = threadIdx.x;
    for (int t=tid; t<CH*DOUT; t+=128) wrs[t] = Wr[t];
    if (tid < DOUT) brs[tid] = br[tid];
    __syncthreads();

    const int row = blockIdx.x*32 + (tid >> 2);
    const int q   = tid & 3;
    const int c0  = q*8;

    float t0x=0.f,t0y=0.f,t0z=0.f,t0w=0.f, t1x=0.f,t1y=0.f,t1z=0.f,t1w=0.f;
    #pragma unroll
    for (int c=0;c<NCHUNK;c++){
        const float* base = &g_part[((size_t)c*NB + row)*CH + c0];
        float4 p0 = *(const float4*)base;
        float4 p1 = *(const float4*)(base+4);
        t0x+=p0.x; t0y+=p0.y; t0z+=p0.z; t0w+=p0.w;
        t1x+=p1.x; t1y+=p1.y; t1z+=p1.z; t1w+=p1.w;
    }
    float4 h0 = *(const float4*)&g_hpre[(size_t)row*CH + c0];
    float4 h1 = *(const float4*)&g_hpre[(size_t)row*CH + c0 + 4];
    float hc[8];
    hc[0] = fmaf(0.05f, t0x, h0.x); hc[1] = fmaf(0.05f, t0y, h0.y);
    hc[2] = fmaf(0.05f, t0z, h0.z); hc[3] = fmaf(0.05f, t0w, h0.w);
    hc[4] = fmaf(0.05f, t1x, h1.x); hc[5] = fmaf(0.05f, t1y, h1.y);
    hc[6] = fmaf(0.05f, t1z, h1.z); hc[7] = fmaf(0.05f, t1w, h1.w);

    float o[DOUT];
    #pragma unroll
    for (int d=0; d<DOUT; d++) o[d] = 0.f;
    #pragma unroll
    for (int u=0;u<8;u++){
        float hcu = hc[u];
        #pragma unroll
        for (int d=0; d<DOUT; d++) o[d] = fmaf(hcu, wrs[(c0+u)*DOUT+d], o[d]);
    }
    #pragma unroll
    for (int off=1; off<4; off<<=1){
        #pragma unroll
        for (int d=0; d<DOUT; d++) o[d] += __shfl_xor_sync(0xffffffffu, o[d], off);
    }
    if (q == 0){
        #pragma unroll
        for (int d=0; d<DOUT; d++) y[(size_t)row*DOUT + d] = o[d] + brs[d];
    }
}

// ---------------- launch ----------------
extern "C" void kernel_launch(void* const* d_in, const int* in_sizes, int n_in,
                              void* d_out, int out_size)
{
    const float* x       = (const float*)d_in[0];
    const float* W1      = (const float*)d_in[1];
    const float* b1      = (const float*)d_in[2];
    const float* W2      = (const float*)d_in[3];
    const float* b2      = (const float*)d_in[4];
    const float* centers = (const float*)d_in[5];
    const float* mus     = (const float*)d_in[6];
    const float* Wp      = (const float*)d_in[7];
    const float* bp      = (const float*)d_in[8];
    const float* Wr      = (const float*)d_in[9];
    const float* br      = (const float*)d_in[10];
    float* y = (float*)d_out;

    enc_kernel<<<NB/32, 256>>>(x, W1, b1, W2, b2, centers, mus, Wp, bp);
    for (int t = 1; t <= TSTEPS; t++){
        lateral_mma_kernel<<<dim3(NB/ITILE, NJS), 256>>>();
        if (t < TSTEPS)
            fused_kernel<<<NB/16, 128>>>(centers, mus, Wp, bp);
    }
    final_kernel<<<NB/32, 128>>>(Wr, br, y);
}

// round 17
// speedup vs baseline: 1.5437x; 1.0114x over previous
#include <cuda_runtime.h>
#include <cuda_bf16.h>
#include <cstdint>

#define NB   4096
#define DIN  784
#define NH   128
#define DL   8
#define NC   16
#define CH   32
#define DOUT 10
#define NCHUNK 8
#define TSTEPS 5

// lateral tiling
#define ITILE 64
#define KC    64
#define NJS   8
#define JRANGE (NB/NJS)     // 512
#define NCH   (JRANGE/KC)   // 8

#define HT_ROW 144              // 72 bf16 per hT row (padded, conflict-free LDS)
#define HT_CHUNK (CH*HT_ROW)    // 4608 B per 64-j chunk
#define ZJ_ROW 48               // 24 bf16 per zj row (16 used)

// ---------------- scratch ----------------
__device__ __align__(16) float g_z[NB*DL];
__device__ float g_sq[NB];                       // CI * |z|^2
__device__ __align__(16) __nv_bfloat16 g_zhl[NB*16];   // [hi0..hi7, lo0..lo7]
__device__ __align__(16) float g_hpre[NB*CH];
__device__ __align__(16) char  g_hT[(NB/KC)*HT_CHUNK]; // bf16 [chunk][ch][72]
__device__ __align__(16) float g_part[(size_t)NCHUNK*NB*CH];

// ---------------- math helpers ----------
__device__ __forceinline__ float ex2f(float x){
    float y; asm("ex2.approx.f32 %0, %1;" : "=f"(y) : "f"(x)); return y;
}
__device__ __forceinline__ float rcp_acc(float x){
    float r; asm("rcp.approx.f32 %0, %1;" : "=f"(r) : "f"(x));
    return r * fmaf(-x, r, 2.0f);
}
__device__ __forceinline__ float rsqrt_acc(float x){
    float r; asm("rsqrt.approx.f32 %0, %1;" : "=f"(r) : "f"(x));
    float e = x * r;
    return r * fmaf(-0.5f, e * r, 1.5f);
}
__device__ __forceinline__ float tanh_acc(float x){
    float ax = fabsf(x);
    float t  = ex2f(-2.8853900817779268f * ax);
    float y  = (1.0f - t) * rcp_acc(1.0f + t);
    return copysignf(y, x);
}

#define CI_F   (-0.50093577808644655f)
#define M2CI_F ( 1.0018715561728931f)

__device__ __forceinline__ uint32_t smem_u32(const void* p){
    uint32_t a;
    asm("{ .reg .u64 t; cvta.to.shared.u64 t, %1; cvt.u32.u64 %0, t; }" : "=r"(a) : "l"(p));
    return a;
}
#define MMA16816(c0,c1,c2,c3,a0,a1,a2,a3,b0,b1) \
    asm volatile("mma.sync.aligned.m16n8k16.row.col.f32.bf16.bf16.f32 " \
        "{%0,%1,%2,%3}, {%4,%5,%6,%7}, {%8,%9}, {%0,%1,%2,%3};" \
        : "+f"(c0),"+f"(c1),"+f"(c2),"+f"(c3) \
        : "r"(a0),"r"(a1),"r"(a2),"r"(a3),"r"(b0),"r"(b1))
#define CVT_BF2(d,hi,lo) asm("cvt.rn.satfinite.bf16x2.f32 %0, %1, %2;" : "=r"(d) : "f"(hi), "f"(lo))
#define LDS32(d, addr) asm volatile("ld.shared.b32 %0, [%1];" : "=r"(d) : "r"(addr))
#define CP16(dst, src) asm volatile("cp.async.cg.shared.global [%0], [%1], 16;" :: "r"(dst), "l"(src) : "memory")
#define CP4(dst, src)  asm volatile("cp.async.ca.shared.global [%0], [%1], 4;"  :: "r"(dst), "l"(src) : "memory")
#define CPCOMMIT() asm volatile("cp.async.commit_group;" ::: "memory")
#define CPWAIT0()  asm volatile("cp.async.wait_group 0;" ::: "memory")
#define CPWAIT1()  asm volatile("cp.async.wait_group 1;" ::: "memory")

// ---- pm field (4 steps), 8 threads per row (2 centers each) ----
__device__ __forceinline__ void pm_oct(float zr[DL], const float* cs,
                                       const float* ms, int o)
{
    #pragma unroll
    for (int step=0; step<4; step++){
        float n = 0.f;
        float g[DL] = {0.f,0.f,0.f,0.f,0.f,0.f,0.f,0.f};
        #pragma unroll
        for (int cc=0;cc<2;cc++){
            int c = o*2 + cc;
            float rv[DL]; float r2 = 1e-4f;
            #pragma unroll
            for (int k=0;k<DL;k++){ rv[k] = zr[k]-cs[c*DL+k]; r2 = fmaf(rv[k],rv[k],r2); }
            float rinv = rsqrt_acc(r2);
            float mr = ms[c]*rinv;
            n += mr;
            float w = mr*rinv*rinv;
            #pragma unroll
            for (int k=0;k<DL;k++) g[k] = fmaf(-w, rv[k], g[k]);
        }
        #pragma unroll
        for (int off=1; off<8; off<<=1){
            n += __shfl_xor_sync(0xffffffffu, n, off);
            #pragma unroll
            for (int k=0;k<DL;k++) g[k] += __shfl_xor_sync(0xffffffffu, g[k], off);
        }
        float s = 0.15f * rcp_acc(n + 1.0f);
        #pragma unroll
        for (int k=0;k<DL;k++)
            zr[k] = fminf(fmaxf(fmaf(s, g[k], zr[k]), -3.f), 3.f);
    }
}

__device__ __forceinline__ void z_store(const float zr[DL], int row)
{
    float s2 = 0.f;
    #pragma unroll
    for (int k=0;k<DL;k++) s2 = fmaf(zr[k], zr[k], s2);
    g_sq[row] = CI_F * s2;
    *(float4*)&g_z[row*DL]   = make_float4(zr[0],zr[1],zr[2],zr[3]);
    *(float4*)&g_z[row*DL+4] = make_float4(zr[4],zr[5],zr[6],zr[7]);
    __nv_bfloat16 hi[8], lo[8];
    #pragma unroll
    for (int k=0;k<DL;k++){
        hi[k] = __float2bfloat16(zr[k]);
        lo[k] = __float2bfloat16(zr[k] - __bfloat162float(hi[k]));
    }
    __nv_bfloat16* dst = &g_zhl[row*16];
    *(uint4*)dst       = *(uint4*)hi;
    *(uint4*)(dst + 8) = *(uint4*)lo;
}

__device__ __forceinline__ void h_update4(const float zr[DL], const float* wps,
                                          const float* bps, int row, int c0,
                                          float4 hc)
{
    float a4[4];
    #pragma unroll
    for (int u=0;u<4;u++) a4[u] = bps[c0+u];
    #pragma unroll
    for (int k=0;k<DL;k++){
        float zk = zr[k];
        #pragma unroll
        for (int u=0;u<4;u++) a4[u] = fmaf(zk, wps[k*CH + c0 + u], a4[u]);
    }
    float4 hv;
    hv.x = fmaf(0.9f, hc.x, 0.1f*tanh_acc(a4[0]));
    hv.y = fmaf(0.9f, hc.y, 0.1f*tanh_acc(a4[1]));
    hv.z = fmaf(0.9f, hc.z, 0.1f*tanh_acc(a4[2]));
    hv.w = fmaf(0.9f, hc.w, 0.1f*tanh_acc(a4[3]));
    *(float4*)&g_hpre[(size_t)row*CH + c0] = hv;
    int jl = row & 63;
    char* base = g_hT + (size_t)(row >> 6) * HT_CHUNK + jl*2;
    *(__nv_bfloat16*)(base + (c0+0)*HT_ROW) = __float2bfloat16(hv.x);
    *(__nv_bfloat16*)(base + (c0+1)*HT_ROW) = __float2bfloat16(hv.y);
    *(__nv_bfloat16*)(base + (c0+2)*HT_ROW) = __float2bfloat16(hv.z);
    *(__nv_bfloat16*)(base + (c0+3)*HT_ROW) = __float2bfloat16(hv.w);
}

// ------ encoder (32 rows/CTA; W1 via cp.async, x via reg pipeline) + prep tail ------
__global__ __launch_bounds__(256) void enc_kernel(
    const float* __restrict__ x, const float* __restrict__ W1,
    const float* __restrict__ b1, const float* __restrict__ W2,
    const float* __restrict__ b2,
    const float* __restrict__ centers, const float* __restrict__ mus,
    const float* __restrict__ Wp, const float* __restrict__ bp)
{
    __shared__ float xs[2][32][33];
    __shared__ __align__(16) float ws[2][32][NH];
    __shared__ float hs[32][NH+1];
    __shared__ float w2s[NH*DL];
    __shared__ float cs[NC*DL];
    __shared__ float ms[NC];
    __shared__ float wps[DL*CH];
    __shared__ float bps[CH];

    const int tid = threadIdx.x;
    const int rowBase = blockIdx.x * 32;
    const int rg = tid >> 4;
    const int cg = tid & 15;

    for (int t = tid; t < NH*DL; t += 256) w2s[t] = W2[t];
    if (tid < NC*DL) cs[tid] = centers[tid];
    if (tid < NC) ms[tid] = mus[tid];
    for (int t = tid; t < DL*CH; t += 256) wps[t] = Wp[t];
    if (tid < CH) bps[tid] = bp[tid];

    const int xr = tid >> 3, xq = tid & 7;
    const float* xsrcRow = &x[(size_t)(rowBase + xr)*DIN];

    #define W1_STAGE(cc, b) do { \
        const int k0_ = (cc)*32; \
        _Pragma("unroll") \
        for (int p_ = 0; p_ < 4; p_++){ \
            int g_ = tid + p_*256; \
            int k_ = g_ >> 5, c4_ = (g_ & 31)*4; \
            int kk_ = k0_ + k_; \
            int ks_ = kk_ < DIN ? kk_ : (DIN-1); \
            CP16(smem_u32(&ws[b][k_][c4_]), (const char*)&W1[(size_t)ks_*NH + c4_]); \
        } \
    } while(0)

    #define X_LOAD(cc, v) do { \
        int kk_ = (cc)*32 + xq*4; \
        (v) = make_float4(0.f,0.f,0.f,0.f); \
        if (kk_ < DIN) (v) = *(const float4*)(xsrcRow + kk_); \
    } while(0)
    #define X_STORE(cc, v) do { \
        float* d_ = &xs[(cc)&1][xr][xq*4]; \
        d_[0]=(v).x; d_[1]=(v).y; d_[2]=(v).z; d_[3]=(v).w; \
    } while(0)

    float acc[2][8];
    #pragma unroll
    for (int a=0;a<2;a++)
        #pragma unroll
        for (int u=0;u<8;u++) acc[a][u]=0.f;

    float4 xv;
    X_LOAD(0, xv);
    X_STORE(0, xv);
    W1_STAGE(0, 0);
    CPCOMMIT();

    for (int c = 0; c < 25; c++){
        float4 xnext;
        if (c + 1 < 25){
            X_LOAD(c+1, xnext);
            W1_STAGE(c+1, (c+1)&1);
            CPCOMMIT();
            CPWAIT1();
        } else {
            CPWAIT0();
        }
        __syncthreads();
        const float (*xsb)[33] = xs[c&1];
        const float (*wsb)[NH] = ws[c&1];
        #pragma unroll
        for (int kk = 0; kk < 32; kk++) {
            float x0 = xsb[rg*2+0][kk];
            float x1 = xsb[rg*2+1][kk];
            float4 w0 = *(const float4*)&wsb[kk][cg*8];
            float4 w1 = *(const float4*)&wsb[kk][cg*8+4];
            acc[0][0] = fmaf(x0, w0.x, acc[0][0]);
            acc[0][1] = fmaf(x0, w0.y, acc[0][1]);
            acc[0][2] = fmaf(x0, w0.z, acc[0][2]);
            acc[0][3] = fmaf(x0, w0.w, acc[0][3]);
            acc[0][4] = fmaf(x0, w1.x, acc[0][4]);
            acc[0][5] = fmaf(x0, w1.y, acc[0][5]);
            acc[0][6] = fmaf(x0, w1.z, acc[0][6]);
            acc[0][7] = fmaf(x0, w1.w, acc[0][7]);
            acc[1][0] = fmaf(x1, w0.x, acc[1][0]);
            acc[1][1] = fmaf(x1, w0.y, acc[1][1]);
            acc[1][2] = fmaf(x1, w0.z, acc[1][2]);
            acc[1][3] = fmaf(x1, w0.w, acc[1][3]);
            acc[1][4] = fmaf(x1, w1.x, acc[1][4]);
            acc[1][5] = fmaf(x1, w1.y, acc[1][5]);
            acc[1][6] = fmaf(x1, w1.z, acc[1][6]);
            acc[1][7] = fmaf(x1, w1.w, acc[1][7]);
        }
        if (c + 1 < 25) X_STORE(c+1, xnext);
        __syncthreads();
    }
    #undef W1_STAGE
    #undef X_LOAD
    #undef X_STORE

    #pragma unroll
    for (int a=0;a<2;a++){
        int r = rg*2+a;
        #pragma unroll
        for (int u=0;u<8;u++){
            int c = cg*8+u;
            hs[r][c] = tanh_acc(acc[a][u] + b1[c]);
        }
    }
    __syncthreads();
    {
        int r = tid >> 3;
        int o = tid & 7;
        float s = b2[o];
        #pragma unroll 16
        for (int k=0;k<NH;k++) s = fmaf(hs[r][k], w2s[k*DL+o], s);
        xs[0][r][o] = s;
    }
    __syncthreads();

    {
        const int r = tid >> 3;
        const int o = tid & 7;
        const int row = rowBase + r;
        float zr[DL];
        #pragma unroll
        for (int k=0;k<DL;k++) zr[k] = xs[0][r][k];
        pm_oct(zr, cs, ms, o);
        if (o == 0) z_store(zr, row);
        h_update4(zr, wps, bps, row, o*4, make_float4(0.f,0.f,0.f,0.f));
    }
}

// ---------- lateral: 4 warps/CTA, ITILE 64, manually 2x-unrolled buffers ----------
__global__ __launch_bounds__(128,8) void lateral_mma_kernel()
{
    __shared__ __align__(16) char zjs[2][KC*ZJ_ROW];
    __shared__ __align__(16) float csq[2][KC];
    __shared__ __align__(16) char hTs[2][HT_CHUNK];

    const int tid  = threadIdx.x;
    const int wid  = tid >> 5;
    const int lane = tid & 31;
    const int grp  = lane >> 2;
    const int t    = lane & 3;
    const int i0 = blockIdx.x * ITILE;
    const int jbase = blockIdx.y * JRANGE;

    const int rowa = i0 + wid*16 + grp;
    const int rowb = rowa + 8;
    uint32_t a0 = *(const uint32_t*)&g_zhl[rowa*16 + 2*t];
    uint32_t a1 = *(const uint32_t*)&g_zhl[rowb*16 + 2*t];
    uint32_t a2 = *(const uint32_t*)&g_zhl[rowa*16 + 8 + 2*t];
    uint32_t a3 = *(const uint32_t*)&g_zhl[rowb*16 + 8 + 2*t];
    const float csia = g_sq[rowa];
    const float csib = g_sq[rowb];

    // per-thread hoisted smem bases (buffer-specific)
    const uint32_t zjT0 = smem_u32(zjs[0]) + grp*ZJ_ROW + 4*t;
    const uint32_t zjT1 = smem_u32(zjs[1]) + grp*ZJ_ROW + 4*t;
    const uint32_t hTT0 = smem_u32(hTs[0]) + grp*HT_ROW + 4*t;
    const uint32_t hTT1 = smem_u32(hTs[1]) + grp*HT_ROW + 4*t;
    const uint32_t zjS0 = smem_u32(zjs[0]);
    const uint32_t zjS1 = smem_u32(zjs[1]);
    const uint32_t hTS0 = smem_u32(hTs[0]);
    const uint32_t hTS1 = smem_u32(hTs[1]);
    const uint32_t cqS0 = smem_u32(csq[0]);
    const uint32_t cqS1 = smem_u32(csq[1]);

    #define STAGE(cc, zjB_, hTB_, cqB_) do { \
        const int j0g_ = jbase + (cc)*KC; \
        { \
            int j_ = tid >> 1, half_ = tid & 1; \
            CP16((zjB_) + j_*ZJ_ROW + half_*16, \
                 (const char*)&g_zhl[(size_t)(j0g_ + j_)*16 + half_*8]); \
        } \
        if (tid < KC) CP4((cqB_) + tid*4, (const char*)&g_sq[j0g_ + tid]); \
        { \
            const char* src_ = g_hT + (size_t)(j0g_ >> 6) * HT_CHUNK; \
            _Pragma("unroll") \
            for (int p_ = 0; p_ < 2; p_++){ \
                int s_ = tid + p_*128; \
                CP16((hTB_) + s_*16, src_ + s_*16); \
            } \
            if (tid < HT_CHUNK/16 - 256) \
                CP16((hTB_) + (tid+256)*16, src_ + (size_t)(tid+256)*16); \
        } \
    } while(0)

    #define COMPUTE(zjT_, hTT_, cq_) do { \
        _Pragma("unroll") \
        for (int ks = 0; ks < 4; ks++){ \
            uint32_t ka[4]; \
            _Pragma("unroll") \
            for (int g = 0; g < 2; g++){ \
                float cc0=0.f, cc1=0.f, cc2=0.f, cc3=0.f; \
                uint32_t b0, b1; \
                LDS32(b0, (zjT_) + (ks*16 + g*8)*ZJ_ROW); \
                LDS32(b1, (zjT_) + (ks*16 + g*8)*ZJ_ROW + 16); \
                MMA16816(cc0,cc1,cc2,cc3, a0,a1,a2,a3, b0,b1); \
                MMA16816(cc0,cc1,cc2,cc3, a0,a1,a2,a3, b1,b0); \
                float2 sj = *(const float2*)&(cq_)[ks*16 + g*8 + 2*t]; \
                float ea0 = fmaf(M2CI_F, cc0, csia + sj.x); \
                float ea1 = fmaf(M2CI_F, cc1, csia + sj.y); \
                float ea2 = fmaf(M2CI_F, cc2, csib + sj.x); \
                float ea3 = fmaf(M2CI_F, cc3, csib + sj.y); \
                float e0 = ex2f(ea0), e1 = ex2f(ea1), e2 = ex2f(ea2), e3 = ex2f(ea3); \
                float p0 = e0*e0, p1 = e1*e1, p2 = e2*e2, p3 = e3*e3; \
                float K0 = fmaf(0.8f, p0*p0, -e0); \
                float K1 = fmaf(0.8f, p1*p1, -e1); \
                float K2 = fmaf(0.8f, p2*p2, -e2); \
                float K3 = fmaf(0.8f, p3*p3, -e3); \
                CVT_BF2(ka[g*2+0], K1, K0); \
                CVT_BF2(ka[g*2+1], K3, K2); \
            } \
            _Pragma("unroll") \
            for (int n = 0; n < 4; n++){ \
                uint32_t hb0, hb1; \
                uint32_t haddr = (hTT_) + n*8*HT_ROW + ks*32; \
                LDS32(hb0, haddr); \
                LDS32(hb1, haddr + 16); \
                MMA16816(hacc[n][0],hacc[n][1],hacc[n][2],hacc[n][3], \
                         ka[0],ka[1],ka[2],ka[3], hb0, hb1); \
            } \
        } \
    } while(0)

    float hacc[4][4];
    #pragma unroll
    for (int n=0;n<4;n++)
        #pragma unroll
        for (int r=0;r<4;r++) hacc[n][r] = 0.f;

    STAGE(0, zjS0, hTS0, cqS0);
    CPCOMMIT();

    #pragma unroll
    for (int c = 0; c < NCH; c += 2){
        CPWAIT0();
        __syncthreads();
        if (c + 1 < NCH){ STAGE(c+1, zjS1, hTS1, cqS1); CPCOMMIT(); }
        COMPUTE(zjT0, hTT0, csq[0]);
        CPWAIT0();
        __syncthreads();
        if (c + 2 < NCH){ STAGE(c+2, zjS0, hTS0, cqS0); CPCOMMIT(); }
        COMPUTE(zjT1, hTT1, csq[1]);
    }
    #undef STAGE
    #undef COMPUTE

    {
        float* d0 = &g_part[((size_t)blockIdx.y*NB + rowa)*CH];
        float* d1 = &g_part[((size_t)blockIdx.y*NB + rowb)*CH];
        #pragma unroll
        for (int n = 0; n < 4; n++){
            *(float2*)&d0[n*8 + 2*t] = make_float2(hacc[n][0], hacc[n][1]);
            *(float2*)&d1[n*8 + 2*t] = make_float2(hacc[n][2], hacc[n][3]);
        }
    }
}

// ------- fused: hcomb = hpre + 0.05*sum(part); z = pm(z); h/hT update -------
__global__ __launch_bounds__(128) void fused_kernel(
    const float* __restrict__ centers, const float* __restrict__ mus,
    const float* __restrict__ Wp, const float* __restrict__ bp)
{
    __shared__ float cs[NC*DL];
    __shared__ float ms[NC];
    __shared__ float wps[DL*CH];
    __shared__ float bps[CH];
    const int tid = threadIdx.x;
    if (tid < NC*DL) cs[tid] = centers[tid];
    if (tid < NC) ms[tid] = mus[tid];
    for (int t = tid; t < DL*CH; t += 128) wps[t] = Wp[t];
    if (tid < CH) bps[tid] = bp[tid];
    __syncthreads();

    const int row = blockIdx.x*16 + (tid >> 3);
    const int o   = tid & 7;
    const int c0  = o*4;

    float tx=0.f, ty=0.f, tz=0.f, tw=0.f;
    #pragma unroll
    for (int c=0;c<NCHUNK;c++){
        float4 p = *(const float4*)&g_part[((size_t)c*NB + row)*CH + c0];
        tx+=p.x; ty+=p.y; tz+=p.z; tw+=p.w;
    }
    float4 h0 = *(const float4*)&g_hpre[(size_t)row*CH + c0];
    float4 hc;
    hc.x = fmaf(0.05f, tx, h0.x);
    hc.y = fmaf(0.05f, ty, h0.y);
    hc.z = fmaf(0.05f, tz, h0.z);
    hc.w = fmaf(0.05f, tw, h0.w);

    float zr[DL];
    {
        float4 a = *(const float4*)&g_z[row*DL];
        float4 b = *(const float4*)&g_z[row*DL+4];
        zr[0]=a.x; zr[1]=a.y; zr[2]=a.z; zr[3]=a.w;
        zr[4]=b.x; zr[5]=b.y; zr[6]=b.z; zr[7]=b.w;
    }
    pm_oct(zr, cs, ms, o);
    if (o == 0) z_store(zr, row);
    h_update4(zr, wps, bps, row, c0, hc);
}

// ------- final: hcomb = hpre + 0.05*sum(part); y = hcomb @ Wr + br -------
__global__ __launch_bounds__(128) void final_kernel(
    const float* __restrict__ Wr, const float* __restrict__ br,
    float* __restrict__ y)
{
    __shared__ float wrs[CH*DOUT];
    __shared__ float brs[DOUT];
    const int tid = threadIdx.x;
    for (int t=tid; t<CH*DOUT; t+=128) wrs[t] = Wr[t];
    if (tid < DOUT) brs[tid] = br[tid];
    __syncthreads();

    const int row = blockIdx.x*32 + (tid >> 2);
    const int q   = tid & 3;
    const int c0  = q*8;

    float t0x=0.f,t0y=0.f,t0z=0.f,t0w=0.f, t1x=0.f,t1y=0.f,t1z=0.f,t1w=0.f;
    #pragma unroll
    for (int c=0;c<NCHUNK;c++){
        const float* base = &g_part[((size_t)c*NB + row)*CH + c0];
        float4 p0 = *(const float4*)base;
        float4 p1 = *(const float4*)(base+4);
        t0x+=p0.x; t0y+=p0.y; t0z+=p0.z; t0w+=p0.w;
        t1x+=p1.x; t1y+=p1.y; t1z+=p1.z; t1w+=p1.w;
    }
    float4 h0 = *(const float4*)&g_hpre[(size_t)row*CH + c0];
    float4 h1 = *(const float4*)&g_hpre[(size_t)row*CH + c0 + 4];
    float hc[8];
    hc[0] = fmaf(0.05f, t0x, h0.x); hc[1] = fmaf(0.05f, t0y, h0.y);
    hc[2] = fmaf(0.05f, t0z, h0.z); hc[3] = fmaf(0.05f, t0w, h0.w);
    hc[4] = fmaf(0.05f, t1x, h1.x); hc[5] = fmaf(0.05f, t1y, h1.y);
    hc[6] = fmaf(0.05f, t1z, h1.z); hc[7] = fmaf(0.05f, t1w, h1.w);

    float o[DOUT];
    #pragma unroll
    for (int d=0; d<DOUT; d++) o[d] = 0.f;
    #pragma unroll
    for (int u=0;u<8;u++){
        float hcu = hc[u];
        #pragma unroll
        for (int d=0; d<DOUT; d++) o[d] = fmaf(hcu, wrs[(c0+u)*DOUT+d], o[d]);
    }
    #pragma unroll
    for (int off=1; off<4; off<<=1){
        #pragma unroll
        for (int d=0; d<DOUT; d++) o[d] += __shfl_xor_sync(0xffffffffu, o[d], off);
    }
    if (q == 0){
        #pragma unroll
        for (int d=0; d<DOUT; d++) y[(size_t)row*DOUT + d] = o[d] + brs[d];
    }
}

// ---------------- launch ----------------
extern "C" void kernel_launch(void* const* d_in, const int* in_sizes, int n_in,
                              void* d_out, int out_size)
{
    const float* x       = (const float*)d_in[0];
    const float* W1      = (const float*)d_in[1];
    const float* b1      = (const float*)d_in[2];
    const float* W2      = (const float*)d_in[3];
    const float* b2      = (const float*)d_in[4];
    const float* centers = (const float*)d_in[5];
    const float* mus     = (const float*)d_in[6];
    const float* Wp      = (const float*)d_in[7];
    const float* bp      = (const float*)d_in[8];
    const float* Wr      = (const float*)d_in[9];
    const float* br      = (const float*)d_in[10];
    float* y = (float*)d_out;

    enc_kernel<<<NB/32, 256>>>(x, W1, b1, W2, b2, centers, mus, Wp, bp);
    for (int t = 1; t <= TSTEPS; t++){
        lateral_mma_kernel<<<dim3(NB/ITILE, NJS), 128>>>();
        if (t < TSTEPS)
            fused_kernel<<<NB/16, 128>>>(centers, mus, Wp, bp);
    }
    final_kernel<<<NB/32, 128>>>(Wr, br, y);
}